// round 7
// baseline (speedup 1.0000x reference)
#include <cuda_runtime.h>

// ForceAggregation: out[m*D + r] = dot(hess[m][r][:], ns[m][:]),  D=300, M=2048.
// hess = 737 MB streamed once. Warp = row pair, depth-1 software pipeline
// (prefetch next pair's 6 LDG.128.LDCS before reducing current pair).
// Tile = 150 rows (2 tiles/molecule, grid 4096): 9-10 pipelined iterations per
// warp so the pipeline-drain fraction drops from 25% to ~11% of iterations.

#define ROWS_PER_BLOCK 150
#define BLOCK_THREADS 256

__device__ __forceinline__ float dot4(float4 a, float4 b, float acc) {
    acc = fmaf(a.x, b.x, acc);
    acc = fmaf(a.y, b.y, acc);
    acc = fmaf(a.z, b.z, acc);
    return fmaf(a.w, b.w, acc);
}

__global__ void __launch_bounds__(BLOCK_THREADS)
force_agg_300(const float* __restrict__ hess,
              const float* __restrict__ ns,
              float* __restrict__ out)
{
    constexpr int D   = 300;
    constexpr int NCH = D / 4;          // 75 float4 chunks per row

    const int m    = blockIdx.x >> 1;
    const int tile = blockIdx.x & 1;
    const int row0 = tile * ROWS_PER_BLOCK;

    const int warp = threadIdx.x >> 5;
    const int lane = threadIdx.x & 31;

    const float4 z4 = make_float4(0.f, 0.f, 0.f, 0.f);

    // ns chunks for this lane — reused by all rows this warp touches.
    const float4* ns4 = (const float4*)(ns + (size_t)m * D);
    const bool has2 = (lane < NCH - 64);
    float4 n0 = __ldg(ns4 + lane);
    float4 n1 = __ldg(ns4 + lane + 32);
    float4 n2 = has2 ? __ldg(ns4 + lane + 64) : z4;

    const float* hbase = hess + (size_t)m * D * D;
    const int    rend  = row0 + ROWS_PER_BLOCK;   // 150 or 300, always <= D, even

    int r = row0 + (warp << 1);

    // ---- prologue: load current pair ----
    const float4* h0 = (const float4*)(hbase + (size_t)r * D);
    const float4* h1 = (const float4*)(hbase + (size_t)(r + 1) * D);
    float4 a0 = __ldcs(h0 + lane);
    float4 b0 = __ldcs(h1 + lane);
    float4 a1 = __ldcs(h0 + lane + 32);
    float4 b1 = __ldcs(h1 + lane + 32);
    float4 a2 = z4, b2 = z4;
    if (has2) { a2 = __ldcs(h0 + lane + 64); b2 = __ldcs(h1 + lane + 64); }

    for (; r < rend; r += 16) {
        // ---- prefetch next pair (kept in flight through the reduce) ----
        const int rn = r + 16;
        const bool more = (rn < rend);
        float4 pa0 = z4, pb0 = z4, pa1 = z4, pb1 = z4, pa2 = z4, pb2 = z4;
        if (more) {
            const float4* g0 = (const float4*)(hbase + (size_t)rn * D);
            const float4* g1 = (const float4*)(hbase + (size_t)(rn + 1) * D);
            pa0 = __ldcs(g0 + lane);
            pb0 = __ldcs(g1 + lane);
            pa1 = __ldcs(g0 + lane + 32);
            pb1 = __ldcs(g1 + lane + 32);
            if (has2) { pa2 = __ldcs(g0 + lane + 64); pb2 = __ldcs(g1 + lane + 64); }
        }

        // ---- compute current pair ----
        float acc0 = dot4(a0, n0, 0.f);
        float acc1 = dot4(b0, n0, 0.f);
        acc0 = dot4(a1, n1, acc0);
        acc1 = dot4(b1, n1, acc1);
        acc0 = dot4(a2, n2, acc0);
        acc1 = dot4(b2, n2, acc1);

        // ---- 6-shuffle paired reduction: lane0 -> r, lane16 -> r+1 ----
        acc0 += __shfl_xor_sync(0xffffffffu, acc0, 16);
        acc1 += __shfl_xor_sync(0xffffffffu, acc1, 16);
        float v = (lane & 16) ? acc1 : acc0;
        v += __shfl_xor_sync(0xffffffffu, v, 8);
        v += __shfl_xor_sync(0xffffffffu, v, 4);
        v += __shfl_xor_sync(0xffffffffu, v, 2);
        v += __shfl_xor_sync(0xffffffffu, v, 1);
        if (lane == 0)       out[(size_t)m * D + r]     = v;
        else if (lane == 16) out[(size_t)m * D + r + 1] = v;

        // ---- rotate pipeline ----
        a0 = pa0; b0 = pb0; a1 = pa1; b1 = pb1; a2 = pa2; b2 = pb2;
    }
}

// Generic fallback for unexpected D (runtime loop bounds, smem-staged ns).
__global__ void __launch_bounds__(BLOCK_THREADS)
force_agg_generic(const float* __restrict__ hess,
                  const float* __restrict__ ns,
                  float* __restrict__ out,
                  int D, int tiles_per_mol, int rows_per_tile)
{
    extern __shared__ __align__(16) float s_ns[];

    const int m    = blockIdx.x / tiles_per_mol;
    const int tile = blockIdx.x - m * tiles_per_mol;
    const int row0 = tile * rows_per_tile;

    const float* nsm = ns + (size_t)m * D;
    const int nch = D >> 2;
    for (int i = threadIdx.x; i < nch; i += BLOCK_THREADS)
        ((float4*)s_ns)[i] = ((const float4*)nsm)[i];
    for (int i = nch * 4 + threadIdx.x; i < D; i += BLOCK_THREADS)
        s_ns[i] = nsm[i];
    __syncthreads();

    const int warp  = threadIdx.x >> 5;
    const int lane  = threadIdx.x & 31;
    const int nwrps = BLOCK_THREADS >> 5;

    const float4* s4    = (const float4*)s_ns;
    const float*  hbase = hess + (size_t)m * D * D;

    int rend = row0 + rows_per_tile;
    if (rend > D) rend = D;

    for (int r = row0 + warp; r < rend; r += nwrps) {
        const float4* hrow = (const float4*)(hbase + (size_t)r * D);
        float acc = 0.0f;
        for (int c = lane; c < nch; c += 32) {
            const float4 h = __ldcs(hrow + c);
            const float4 n = s4[c];
            acc = fmaf(h.x, n.x, acc);
            acc = fmaf(h.y, n.y, acc);
            acc = fmaf(h.z, n.z, acc);
            acc = fmaf(h.w, n.w, acc);
        }
        for (int c = nch * 4 + lane; c < D; c += 32)
            acc = fmaf(hbase[(size_t)r * D + c], s_ns[c], acc);
#pragma unroll
        for (int off = 16; off; off >>= 1)
            acc += __shfl_xor_sync(0xffffffffu, acc, off);
        if (lane == 0)
            out[(size_t)m * D + r] = acc;
    }
}

extern "C" void kernel_launch(void* const* d_in, const int* in_sizes, int n_in,
                              void* d_out, int out_size)
{
    // Input order: ns [M*N_AT,3] f32, hess [M*D,D] f32, idx_m i32, n_atoms [M] i32
    const float* ns   = (const float*)d_in[0];
    const float* hess = (const float*)d_in[1];
    float*       out  = (float*)d_out;

    const int M = in_sizes[3];
    const int D = (int)((long long)in_sizes[0] / M);

    if (D == 300) {
        force_agg_300<<<(unsigned)(M * 2), BLOCK_THREADS>>>(hess, ns, out);
    } else {
        const int rows = 64;
        const int tiles = (D + rows - 1) / rows;
        const size_t shmem = (size_t)((D + 3) / 4) * 16;
        force_agg_generic<<<(unsigned)(M * tiles), BLOCK_THREADS, shmem>>>(hess, ns, out, D, tiles, rows);
    }
}

// round 8
// speedup vs baseline: 1.0121x; 1.0121x over previous
#include <cuda_runtime.h>

// ForceAggregation: out[m*D + r] = dot(hess[m][r][:], ns[m][:]),  D=300, M=2048.
// hess = 737 MB streamed once. Proven macro-shape (R6): grid 10240, 64-row tiles,
// warp = row pair, depth-1 prefetch pipeline, 6-shuffle paired reduce.
// This round: full tiles use a COMPILE-TIME 4-iteration unrolled pipeline
// (static prefetch predicates, strength-reduced addressing) to cut ALU overhead;
// the 44-row tail tile keeps the runtime-pipelined loop.

#define BLOCK_THREADS 256
#define D300 300

struct P6 { float4 a0, b0, a1, b1, a2, b2; };

__device__ __forceinline__ float4 f4z() { return make_float4(0.f, 0.f, 0.f, 0.f); }

__device__ __forceinline__ P6 load_pair(const float* __restrict__ hb, int lane, bool has2) {
    const float4* h0 = (const float4*)hb;
    const float4* h1 = (const float4*)(hb + D300);
    P6 p;
    p.a0 = __ldcs(h0 + lane);
    p.b0 = __ldcs(h1 + lane);
    p.a1 = __ldcs(h0 + lane + 32);
    p.b1 = __ldcs(h1 + lane + 32);
    p.a2 = f4z(); p.b2 = f4z();
    if (has2) { p.a2 = __ldcs(h0 + lane + 64); p.b2 = __ldcs(h1 + lane + 64); }
    return p;
}

__device__ __forceinline__ float dot4(float4 a, float4 b, float acc) {
    acc = fmaf(a.x, b.x, acc);
    acc = fmaf(a.y, b.y, acc);
    acc = fmaf(a.z, b.z, acc);
    return fmaf(a.w, b.w, acc);
}

// Compute both dot products, reduce (6 shuffles), store rows r and r+1.
__device__ __forceinline__ void compute_store(const P6& p, float4 n0, float4 n1, float4 n2,
                                              float* __restrict__ orow, int lane) {
    float acc0 = dot4(p.a0, n0, 0.f);
    float acc1 = dot4(p.b0, n0, 0.f);
    acc0 = dot4(p.a1, n1, acc0);
    acc1 = dot4(p.b1, n1, acc1);
    acc0 = dot4(p.a2, n2, acc0);
    acc1 = dot4(p.b2, n2, acc1);

    acc0 += __shfl_xor_sync(0xffffffffu, acc0, 16);
    acc1 += __shfl_xor_sync(0xffffffffu, acc1, 16);
    float v = (lane & 16) ? acc1 : acc0;
    v += __shfl_xor_sync(0xffffffffu, v, 8);
    v += __shfl_xor_sync(0xffffffffu, v, 4);
    v += __shfl_xor_sync(0xffffffffu, v, 2);
    v += __shfl_xor_sync(0xffffffffu, v, 1);
    if (lane == 0)       orow[0] = v;
    else if (lane == 16) orow[1] = v;
}

__global__ void __launch_bounds__(BLOCK_THREADS)
force_agg_300(const float* __restrict__ hess,
              const float* __restrict__ ns,
              float* __restrict__ out)
{
    constexpr int NCH = D300 / 4;          // 75

    const int m    = blockIdx.x / 5;
    const int tile = blockIdx.x - m * 5;
    const int row0 = tile << 6;            // 64-row tiles; tile 4 -> rows 256..299

    const int warp = threadIdx.x >> 5;
    const int lane = threadIdx.x & 31;

    // ns chunks for this lane — reused by all rows this warp touches.
    const float4* ns4 = (const float4*)(ns + (size_t)m * D300);
    const bool has2 = (lane < NCH - 64);
    const float4 n0 = __ldg(ns4 + lane);
    const float4 n1 = __ldg(ns4 + lane + 32);
    const float4 n2 = has2 ? __ldg(ns4 + lane + 64) : f4z();

    const float* hbase = hess + (size_t)m * D300 * D300;
    float*       omol  = out + (size_t)m * D300;

    const int r_start = row0 + (warp << 1);
    const float* hb = hbase + (size_t)r_start * D300;

    if (tile < 4) {
        // ---- full tile: exactly 4 pipelined iterations, fully unrolled ----
        P6 cur = load_pair(hb, lane, has2);
#pragma unroll
        for (int i = 0; i < 4; ++i) {
            P6 nxt;
            if (i < 3) nxt = load_pair(hb + (size_t)16 * D300, lane, has2);
            compute_store(cur, n0, n1, n2, omol + r_start + 16 * i, lane);
            if (i < 3) { cur = nxt; hb += (size_t)16 * D300; }
        }
    } else {
        // ---- tail tile: rows 256..299 (22 pairs; warps do 3 or 2 iterations) ----
        int r = r_start;                   // 256 + 2*warp, always < 300
        P6 cur = load_pair(hb, lane, has2);
        for (; r < D300; r += 16) {
            const bool more = (r + 16 < D300);
            P6 nxt;
            if (more) nxt = load_pair(hbase + (size_t)(r + 16) * D300, lane, has2);
            compute_store(cur, n0, n1, n2, omol + r, lane);
            if (more) cur = nxt;
        }
    }
}

// Generic fallback for unexpected D (runtime loop bounds, smem-staged ns).
__global__ void __launch_bounds__(BLOCK_THREADS)
force_agg_generic(const float* __restrict__ hess,
                  const float* __restrict__ ns,
                  float* __restrict__ out,
                  int D, int tiles_per_mol, int rows_per_tile)
{
    extern __shared__ __align__(16) float s_ns[];

    const int m    = blockIdx.x / tiles_per_mol;
    const int tile = blockIdx.x - m * tiles_per_mol;
    const int row0 = tile * rows_per_tile;

    const float* nsm = ns + (size_t)m * D;
    const int nch = D >> 2;
    for (int i = threadIdx.x; i < nch; i += BLOCK_THREADS)
        ((float4*)s_ns)[i] = ((const float4*)nsm)[i];
    for (int i = nch * 4 + threadIdx.x; i < D; i += BLOCK_THREADS)
        s_ns[i] = nsm[i];
    __syncthreads();

    const int warp  = threadIdx.x >> 5;
    const int lane  = threadIdx.x & 31;
    const int nwrps = BLOCK_THREADS >> 5;

    const float4* s4    = (const float4*)s_ns;
    const float*  hbase = hess + (size_t)m * D * D;

    int rend = row0 + rows_per_tile;
    if (rend > D) rend = D;

    for (int r = row0 + warp; r < rend; r += nwrps) {
        const float4* hrow = (const float4*)(hbase + (size_t)r * D);
        float acc = 0.0f;
        for (int c = lane; c < nch; c += 32) {
            const float4 h = __ldcs(hrow + c);
            const float4 n = s4[c];
            acc = fmaf(h.x, n.x, acc);
            acc = fmaf(h.y, n.y, acc);
            acc = fmaf(h.z, n.z, acc);
            acc = fmaf(h.w, n.w, acc);
        }
        for (int c = nch * 4 + lane; c < D; c += 32)
            acc = fmaf(hbase[(size_t)r * D + c], s_ns[c], acc);
#pragma unroll
        for (int off = 16; off; off >>= 1)
            acc += __shfl_xor_sync(0xffffffffu, acc, off);
        if (lane == 0)
            out[(size_t)m * D + r] = acc;
    }
}

extern "C" void kernel_launch(void* const* d_in, const int* in_sizes, int n_in,
                              void* d_out, int out_size)
{
    // Input order: ns [M*N_AT,3] f32, hess [M*D,D] f32, idx_m i32, n_atoms [M] i32
    const float* ns   = (const float*)d_in[0];
    const float* hess = (const float*)d_in[1];
    float*       out  = (float*)d_out;

    const int M = in_sizes[3];
    const int D = (int)((long long)in_sizes[0] / M);

    if (D == 300) {
        force_agg_300<<<(unsigned)(M * 5), BLOCK_THREADS>>>(hess, ns, out);
    } else {
        const int rows = 64;
        const int tiles = (D + rows - 1) / rows;
        const size_t shmem = (size_t)((D + 3) / 4) * 16;
        force_agg_generic<<<(unsigned)(M * tiles), BLOCK_THREADS, shmem>>>(hess, ns, out, D, tiles, rows);
    }
}